// round 1
// baseline (speedup 1.0000x reference)
#include <cuda_runtime.h>
#include <math.h>

// Problem dims (fixed by the dataset)
#define NN   50000
#define DIN  100
#define DHID 256
#define DOUT 40

// ---------------- scratch (device globals: no allocations allowed) ----------------
__device__ float g_agg1[(size_t)NN * DIN];     // 20 MB : x + scatter(x)
__device__ float g_h1  [(size_t)NN * DHID];    // 51 MB : agg1 @ W1 (pre-BN)
__device__ float g_y2  [(size_t)NN * DOUT];    // 8 MB  : relu(BN(h1)) @ W2
__device__ float g_agg2[(size_t)NN * DOUT];    // 8 MB  : y2 + scatter(y2)
__device__ float g_sum1[DHID], g_sq1[DHID], g_scale1[DHID], g_shift1[DHID];
__device__ float g_sum2[DOUT], g_sq2[DOUT], g_sc2[DOUT], g_sh2[DOUT];
__device__ int   g_ei64;

// ---------------- helpers ----------------
__device__ __forceinline__ void red_add_v4(float* p, float4 v) {
    asm volatile("red.global.add.v4.f32 [%0], {%1,%2,%3,%4};"
                 :: "l"(p), "f"(v.x), "f"(v.y), "f"(v.z), "f"(v.w) : "memory");
}

__device__ __forceinline__ void load_edge(const void* ei, int E, int e, int& s, int& d) {
    if (g_ei64) {
        const long long* p = (const long long*)ei;
        s = (int)p[e]; d = (int)p[E + e];
    } else {
        const int* p = (const int*)ei;
        s = p[e]; d = p[E + e];
    }
}

// ---------------- kernels ----------------

// Detect int64 vs int32 edge_index: for int64 values in [0,50000), every odd
// int32 word (the high half) is 0. Probability of that for 32 random int32
// values in [0,50000) is ~0.
__global__ void k_detect(const int* ei) {
    int l = threadIdx.x;
    int v = ei[2 * l + 1];
    unsigned b = __ballot_sync(0xffffffffu, v == 0);
    if (l == 0) g_ei64 = (b == 0xffffffffu) ? 1 : 0;
}

__global__ void k_zero_stats() {
    int t = threadIdx.x;
    if (t < DHID) { g_sum1[t] = 0.f; g_sq1[t] = 0.f; }
    if (t < DOUT) { g_sum2[t] = 0.f; g_sq2[t] = 0.f; }
}

// agg1 = x  (vectorized copy; DIN*N divisible by 4)
__global__ void k_copy_x(const float4* __restrict__ x, int n4) {
    int i = blockIdx.x * blockDim.x + threadIdx.x;
    if (i < n4) ((float4*)g_agg1)[i] = x[i];
}

// agg1[dst] += x[src], 25 float4 per edge
__global__ void k_scatter1(const float* __restrict__ x, const void* __restrict__ ei,
                           int E, int items) {
    int idx = blockIdx.x * blockDim.x + threadIdx.x;
    if (idx >= items) return;
    int e = idx / 25, c = idx - e * 25;
    int s, d;
    load_edge(ei, E, e, s, d);
    float4 v = ((const float4*)x)[s * 25 + c];
    red_add_v4(&g_agg1[d * DIN + c * 4], v);
}

// h1 = agg1 @ W1   (M x 100) @ (100 x 256), fp32 SIMT, BM=BN=128, BK=20
__global__ void __launch_bounds__(256) k_gemm1(const float* __restrict__ W1, int M) {
    __shared__ float As[20][132];  // +4 pad keeps float4 alignment
    __shared__ float Bs[20][128];
    int tid = threadIdx.x;
    int tx = tid & 15, ty = tid >> 4;
    int row0 = blockIdx.x * 128, col0 = blockIdx.y * 128;

    float acc[8][8];
#pragma unroll
    for (int i = 0; i < 8; i++)
#pragma unroll
        for (int j = 0; j < 8; j++) acc[i][j] = 0.f;

    for (int kt = 0; kt < 5; kt++) {
        int k0 = kt * 20;
#pragma unroll
        for (int j = 0; j < 10; j++) {           // A tile: 128x20
            int idx = tid + 256 * j;
            int m = idx / 20, k = idx - m * 20;
            int r = row0 + m;
            As[k][m] = (r < M) ? g_agg1[r * DIN + k0 + k] : 0.f;
        }
#pragma unroll
        for (int j = 0; j < 10; j++) {           // B tile: 20x128
            int idx = tid + 256 * j;
            int k = idx >> 7, n = idx & 127;
            Bs[k][n] = W1[(k0 + k) * DHID + col0 + n];
        }
        __syncthreads();
#pragma unroll
        for (int k = 0; k < 20; k++) {
            float4 a0 = *(const float4*)&As[k][ty * 8];
            float4 a1 = *(const float4*)&As[k][ty * 8 + 4];
            float4 b0 = *(const float4*)&Bs[k][tx * 8];
            float4 b1 = *(const float4*)&Bs[k][tx * 8 + 4];
            float a[8] = {a0.x, a0.y, a0.z, a0.w, a1.x, a1.y, a1.z, a1.w};
            float b[8] = {b0.x, b0.y, b0.z, b0.w, b1.x, b1.y, b1.z, b1.w};
#pragma unroll
            for (int i = 0; i < 8; i++)
#pragma unroll
                for (int j = 0; j < 8; j++) acc[i][j] = fmaf(a[i], b[j], acc[i][j]);
        }
        __syncthreads();
    }
#pragma unroll
    for (int i = 0; i < 8; i++) {
        int r = row0 + ty * 8 + i;
        if (r < M) {
            float* o = &g_h1[(size_t)r * DHID + col0 + tx * 8];
            float4 v0 = {acc[i][0], acc[i][1], acc[i][2], acc[i][3]};
            float4 v1 = {acc[i][4], acc[i][5], acc[i][6], acc[i][7]};
            *(float4*)o = v0;
            *(float4*)(o + 4) = v1;
        }
    }
}

// column sums / sumsq of h1
__global__ void k_stats1(int M) {
    int c = threadIdx.x;  // 256 threads = 256 columns
    int r0 = blockIdx.x * 256;
    int r1 = min(r0 + 256, M);
    float s = 0.f, q = 0.f;
    for (int r = r0; r < r1; r++) {
        float v = g_h1[(size_t)r * DHID + c];
        s += v; q = fmaf(v, v, q);
    }
    atomicAdd(&g_sum1[c], s);
    atomicAdd(&g_sq1[c], q);
}

__global__ void k_fin1(const float* __restrict__ gamma, const float* __restrict__ beta,
                       float invN) {
    int c = threadIdx.x;
    float mean = g_sum1[c] * invN;
    float var = g_sq1[c] * invN - mean * mean;
    float sc = gamma[c] * rsqrtf(var + 1e-5f);
    g_scale1[c] = sc;
    g_shift1[c] = beta[c] - mean * sc;
}

// y2 = relu(h1*scale1+shift1) @ W2 ; also init agg2 = y2.
// BM=64 rows, N=40 full, BK=32, 128 threads: thread = (cx 0..7)x(ry 0..15),
// computes 4 rows x 5 cols.
__global__ void __launch_bounds__(128) k_gemm2(const float* __restrict__ W2, int M) {
    __shared__ float As[64][33];
    __shared__ float Bs[32][DOUT];
    int tid = threadIdx.x;
    int cx = tid & 7, ry = tid >> 3;
    int row0 = blockIdx.x * 64;

    float acc[4][5];
#pragma unroll
    for (int i = 0; i < 4; i++)
#pragma unroll
        for (int j = 0; j < 5; j++) acc[i][j] = 0.f;

    for (int kt = 0; kt < 8; kt++) {
        int k0 = kt * 32;
#pragma unroll
        for (int j = 0; j < 16; j++) {           // A tile 64x32, normalized + relu
            int idx = tid + 128 * j;
            int m = idx >> 5, k = idx & 31;
            int r = row0 + m;
            float v = 0.f;
            if (r < M) {
                v = g_h1[(size_t)r * DHID + k0 + k];
                v = fmaxf(fmaf(v, g_scale1[k0 + k], g_shift1[k0 + k]), 0.f);
            }
            As[m][k] = v;
        }
#pragma unroll
        for (int j = 0; j < 10; j++) {           // B tile 32x40
            int idx = tid + 128 * j;
            int k = idx / 40, n = idx - k * 40;
            Bs[k][n] = W2[(k0 + k) * DOUT + n];
        }
        __syncthreads();
#pragma unroll
        for (int k = 0; k < 32; k++) {
            float a[4], b[5];
#pragma unroll
            for (int i = 0; i < 4; i++) a[i] = As[ry * 4 + i][k];
#pragma unroll
            for (int j = 0; j < 5; j++) b[j] = Bs[k][cx * 5 + j];
#pragma unroll
            for (int i = 0; i < 4; i++)
#pragma unroll
                for (int j = 0; j < 5; j++) acc[i][j] = fmaf(a[i], b[j], acc[i][j]);
        }
        __syncthreads();
    }
#pragma unroll
    for (int i = 0; i < 4; i++) {
        int r = row0 + ry * 4 + i;
        if (r < M) {
#pragma unroll
            for (int j = 0; j < 5; j++) {
                int o = r * DOUT + cx * 5 + j;
                float v = acc[i][j];
                g_y2[o] = v;
                g_agg2[o] = v;
            }
        }
    }
}

// agg2[dst] += y2[src], 10 float4 per edge
__global__ void k_scatter2(const void* __restrict__ ei, int E, int items) {
    int idx = blockIdx.x * blockDim.x + threadIdx.x;
    if (idx >= items) return;
    int e = idx / 10, c = idx - e * 10;
    int s, d;
    load_edge(ei, E, e, s, d);
    float4 v = ((const float4*)g_y2)[s * 10 + c];
    red_add_v4(&g_agg2[d * DOUT + c * 4], v);
}

// column sums / sumsq of agg2 (40 cols). blockDim = 160 = 40 cols x 4 row-lanes.
__global__ void k_stats2(int M) {
    __shared__ float ssum[160], ssq[160];
    int t = threadIdx.x;
    int c = t % 40, rr = t / 40;
    int rpb = (M + gridDim.x - 1) / gridDim.x;
    int r0 = blockIdx.x * rpb;
    int r1 = min(r0 + rpb, M);
    float s = 0.f, q = 0.f;
    for (int r = r0 + rr; r < r1; r += 4) {
        float v = g_agg2[r * DOUT + c];
        s += v; q = fmaf(v, v, q);
    }
    ssum[t] = s; ssq[t] = q;
    __syncthreads();
    if (t < 40) {
        float S = ssum[t] + ssum[t + 40] + ssum[t + 80] + ssum[t + 120];
        float Q = ssq[t] + ssq[t + 40] + ssq[t + 80] + ssq[t + 120];
        atomicAdd(&g_sum2[t], S);
        atomicAdd(&g_sq2[t], Q);
    }
}

__global__ void k_fin2(const float* __restrict__ gamma, const float* __restrict__ beta,
                       float invN) {
    int c = threadIdx.x;
    if (c >= DOUT) return;
    float mean = g_sum2[c] * invN;
    float var = g_sq2[c] * invN - mean * mean;
    float sc = gamma[c] * rsqrtf(var + 1e-5f);
    g_sc2[c] = sc;
    g_sh2[c] = beta[c] - mean * sc;
}

// per-row: normalize + log_softmax. One warp per row; lane l covers cols l and
// (l<8) 32+l.
__global__ void k_logsoftmax(float* __restrict__ out, int M) {
    int w = (blockIdx.x * blockDim.x + threadIdx.x) >> 5;
    int l = threadIdx.x & 31;
    if (w >= M) return;
    const float* a = &g_agg2[w * DOUT];
    float v0 = fmaf(a[l], g_sc2[l], g_sh2[l]);
    float v1 = (l < 8) ? fmaf(a[32 + l], g_sc2[32 + l], g_sh2[32 + l]) : -1e30f;
    float m = fmaxf(v0, v1);
#pragma unroll
    for (int o = 16; o > 0; o >>= 1) m = fmaxf(m, __shfl_xor_sync(0xffffffffu, m, o));
    float e = expf(v0 - m) + ((l < 8) ? expf(v1 - m) : 0.f);
#pragma unroll
    for (int o = 16; o > 0; o >>= 1) e += __shfl_xor_sync(0xffffffffu, e, o);
    float ls = m + logf(e);
    out[w * DOUT + l] = v0 - ls;
    if (l < 8) out[w * DOUT + 32 + l] = v1 - ls;
}

// ---------------- launch ----------------
extern "C" void kernel_launch(void* const* d_in, const int* in_sizes, int n_in,
                              void* d_out, int out_size) {
    const float* x      = (const float*)d_in[0];
    const void*  ei     = d_in[1];
    const float* W1     = (const float*)d_in[2];
    // d_in[3] = b1 : absorbed by BN, unused
    const float* W2     = (const float*)d_in[4];
    // d_in[5] = b2 : absorbed by BN, unused
    const float* gamma1 = (const float*)d_in[6];
    const float* beta1  = (const float*)d_in[7];
    const float* gamma2 = (const float*)d_in[8];
    const float* beta2  = (const float*)d_in[9];
    float* out = (float*)d_out;

    int N = in_sizes[0] / DIN;     // 50000
    int E = in_sizes[1] / 2;       // 800000 (element count same for i32/i64)
    float invN = 1.0f / (float)N;

    k_detect<<<1, 32>>>((const int*)ei);
    k_zero_stats<<<1, 256>>>();

    int n4 = N * DIN / 4;
    k_copy_x<<<(n4 + 255) / 256, 256>>>((const float4*)x, n4);

    int it1 = E * 25;
    k_scatter1<<<(it1 + 255) / 256, 256>>>(x, ei, E, it1);

    dim3 g1((N + 127) / 128, DHID / 128);
    k_gemm1<<<g1, 256>>>(W1, N);

    k_stats1<<<(N + 255) / 256, 256>>>(N);
    k_fin1<<<1, DHID>>>(gamma1, beta1, invN);

    k_gemm2<<<(N + 63) / 64, 128>>>(W2, N);

    int it2 = E * 10;
    k_scatter2<<<(it2 + 255) / 256, 256>>>(ei, E, it2);

    k_stats2<<<128, 160>>>(N);
    k_fin2<<<1, 64>>>(gamma2, beta2, invN);

    k_logsoftmax<<<(N + 7) / 8, 256>>>(out, N);
}

// round 2
// speedup vs baseline: 1.1759x; 1.1759x over previous
#include <cuda_runtime.h>
#include <math.h>

// Problem dims (fixed by the dataset)
#define NN   50000
#define DIN  100
#define DHID 256
#define DOUT 40

// ---------------- scratch (device globals: no allocations allowed) ----------------
__device__ float g_agg1[(size_t)NN * DIN];     // 20 MB : x + scatter(x)
__device__ float g_h1  [(size_t)NN * DHID];    // 51 MB : agg1 @ W1 (pre-BN)
__device__ float g_y2  [(size_t)NN * DOUT];    // 8 MB  : relu(BN(h1)) @ W2
__device__ float g_agg2[(size_t)NN * DOUT];    // 8 MB  : y2 + scatter(y2)
__device__ float g_sum1[DHID], g_sq1[DHID], g_scale1[DHID], g_shift1[DHID];
__device__ float g_sum2[DOUT], g_sq2[DOUT], g_sc2[DOUT], g_sh2[DOUT];
__device__ int   g_ei64;

// ---------------- helpers ----------------
__device__ __forceinline__ void red_add_v4(float* p, float4 v) {
    asm volatile("red.global.add.v4.f32 [%0], {%1,%2,%3,%4};"
                 :: "l"(p), "f"(v.x), "f"(v.y), "f"(v.z), "f"(v.w) : "memory");
}

__device__ __forceinline__ void load_edge(const void* ei, int E, int e, int& s, int& d) {
    if (g_ei64) {
        const long long* p = (const long long*)ei;
        s = (int)p[e]; d = (int)p[E + e];
    } else {
        const int* p = (const int*)ei;
        s = p[e]; d = p[E + e];
    }
}

__device__ __forceinline__ unsigned f2tf(float f) {
    unsigned r;
    asm("cvt.rna.tf32.f32 %0, %1;" : "=r"(r) : "f"(f));
    return r;
}

// ---------------- kernels ----------------

// Detect int64 vs int32 edge_index (high words of in-range int64 are all 0).
__global__ void k_detect(const int* ei) {
    int l = threadIdx.x;
    int v = ei[2 * l + 1];
    unsigned b = __ballot_sync(0xffffffffu, v == 0);
    if (l == 0) g_ei64 = (b == 0xffffffffu) ? 1 : 0;
}

__global__ void k_zero_stats() {
    int t = threadIdx.x;
    if (t < DHID) { g_sum1[t] = 0.f; g_sq1[t] = 0.f; }
    if (t < DOUT) { g_sum2[t] = 0.f; g_sq2[t] = 0.f; }
}

// agg1 = x
__global__ void k_copy_x(const float4* __restrict__ x, int n4) {
    int i = blockIdx.x * blockDim.x + threadIdx.x;
    if (i < n4) ((float4*)g_agg1)[i] = x[i];
}

// agg1[dst] += x[src], 25 float4 per edge
__global__ void k_scatter1(const float* __restrict__ x, const void* __restrict__ ei,
                           int E, int items) {
    int idx = blockIdx.x * blockDim.x + threadIdx.x;
    if (idx >= items) return;
    int e = idx / 25, c = idx - e * 25;
    int s, d;
    load_edge(ei, E, e, s, d);
    float4 v = ((const float4*)x)[s * 25 + c];
    red_add_v4(&g_agg1[d * DIN + c * 4], v);
}

// ---- gemm1: h1 = agg1 @ W1 via tf32 mma.sync, with fused BN stats ----
// BM=128, BN=128, K padded 100->104, full K resident in smem.
// smem: As[128][108] (stride 108 == 12 mod 32: conflict-free A frags)
//       Bs[104][136] (stride 136 ==  8 mod 32: conflict-free B frags)
#define AS_STRIDE 108
#define BS_STRIDE 136
#define KPAD 104

__global__ void __launch_bounds__(256) k_gemm1_tf32(const float* __restrict__ W1, int M) {
    extern __shared__ unsigned sm[];
    unsigned* As = sm;                      // 128*108
    unsigned* Bs = sm + 128 * AS_STRIDE;    // 104*136

    int tid = threadIdx.x;
    int lane = tid & 31, warp = tid >> 5;
    int warp_m = warp >> 1;     // 0..3 -> rows warp_m*32
    int warp_n = warp & 1;      // 0..1 -> cols warp_n*64
    int grp = lane >> 2, qd = lane & 3;
    int row0 = blockIdx.x * 128, col0 = blockIdx.y * 128;

    // ---- load A tile (agg1 rows, convert to tf32) ----
    {
        int m = tid >> 1, h = tid & 1;
        int r = row0 + m;
        unsigned* dst = &As[m * AS_STRIDE + h * 52];
        if (r < M) {
            const float4* src = (const float4*)&g_agg1[r * DIN + h * 52];
            int nv4 = h ? 12 : 13;
#pragma unroll
            for (int i = 0; i < 13; i++) {
                if (i < nv4) {
                    float4 v = src[i];
                    dst[i * 4 + 0] = f2tf(v.x);
                    dst[i * 4 + 1] = f2tf(v.y);
                    dst[i * 4 + 2] = f2tf(v.z);
                    dst[i * 4 + 3] = f2tf(v.w);
                }
            }
            if (h) { dst[48] = 0; dst[49] = 0; dst[50] = 0; dst[51] = 0; } // cols 100..103
        } else {
#pragma unroll
            for (int i = 0; i < 52; i++) dst[i] = 0;
        }
    }
    // ---- load B tile (W1 rows) ----
    if (tid < 208) {
        int k = tid >> 1, h = tid & 1;
        unsigned* dst = &Bs[k * BS_STRIDE + h * 64];
        if (k < DIN) {
            const float4* src = (const float4*)&W1[k * DHID + col0 + h * 64];
#pragma unroll
            for (int i = 0; i < 16; i++) {
                float4 v = src[i];
                dst[i * 4 + 0] = f2tf(v.x);
                dst[i * 4 + 1] = f2tf(v.y);
                dst[i * 4 + 2] = f2tf(v.z);
                dst[i * 4 + 3] = f2tf(v.w);
            }
        } else {
#pragma unroll
            for (int i = 0; i < 64; i++) dst[i] = 0;
        }
    }
    __syncthreads();

    float acc[2][8][4];
#pragma unroll
    for (int mt = 0; mt < 2; mt++)
#pragma unroll
        for (int nt = 0; nt < 8; nt++)
#pragma unroll
            for (int j = 0; j < 4; j++) acc[mt][nt][j] = 0.f;

    for (int ks = 0; ks < KPAD / 8; ks++) {
        int k0 = ks * 8;
        unsigned a[2][4];
#pragma unroll
        for (int mt = 0; mt < 2; mt++) {
            const unsigned* Ar  = &As[(warp_m * 32 + mt * 16 + grp) * AS_STRIDE + k0 + qd];
            const unsigned* Ar8 = Ar + 8 * AS_STRIDE;
            a[mt][0] = Ar[0];  a[mt][1] = Ar8[0];
            a[mt][2] = Ar[4];  a[mt][3] = Ar8[4];
        }
#pragma unroll
        for (int nt = 0; nt < 8; nt++) {
            const unsigned* Bp = &Bs[(k0 + qd) * BS_STRIDE + warp_n * 64 + nt * 8 + grp];
            unsigned b0 = Bp[0];
            unsigned b1 = Bp[4 * BS_STRIDE];
#pragma unroll
            for (int mt = 0; mt < 2; mt++) {
                asm volatile(
                    "mma.sync.aligned.m16n8k8.row.col.f32.tf32.tf32.f32 "
                    "{%0,%1,%2,%3},{%4,%5,%6,%7},{%8,%9},{%0,%1,%2,%3};"
                    : "+f"(acc[mt][nt][0]), "+f"(acc[mt][nt][1]),
                      "+f"(acc[mt][nt][2]), "+f"(acc[mt][nt][3])
                    : "r"(a[mt][0]), "r"(a[mt][1]), "r"(a[mt][2]), "r"(a[mt][3]),
                      "r"(b0), "r"(b1));
            }
        }
    }

    // ---- epilogue: store h1 + fused column stats ----
    // D frag: d0=(grp,2qd) d1=(grp,2qd+1) d2=(grp+8,2qd) d3=(grp+8,2qd+1)
#pragma unroll
    for (int nt = 0; nt < 8; nt++) {
        int c = col0 + warp_n * 64 + nt * 8 + 2 * qd;
        float s0 = 0.f, s1 = 0.f, q0 = 0.f, q1 = 0.f;
#pragma unroll
        for (int mt = 0; mt < 2; mt++) {
            int r = row0 + warp_m * 32 + mt * 16 + grp;
            float d0 = acc[mt][nt][0], d1 = acc[mt][nt][1];
            float d2 = acc[mt][nt][2], d3 = acc[mt][nt][3];
            if (r < M)     *(float2*)&g_h1[(size_t)r * DHID + c] = make_float2(d0, d1);
            if (r + 8 < M) *(float2*)&g_h1[(size_t)(r + 8) * DHID + c] = make_float2(d2, d3);
            s0 += d0 + d2;  s1 += d1 + d3;
            q0 = fmaf(d0, d0, fmaf(d2, d2, q0));
            q1 = fmaf(d1, d1, fmaf(d3, d3, q1));
        }
        // reduce over the 8 lanes sharing qd (strides 4,8,16)
#pragma unroll
        for (int o = 4; o < 32; o <<= 1) {
            s0 += __shfl_xor_sync(0xffffffffu, s0, o);
            s1 += __shfl_xor_sync(0xffffffffu, s1, o);
            q0 += __shfl_xor_sync(0xffffffffu, q0, o);
            q1 += __shfl_xor_sync(0xffffffffu, q1, o);
        }
        if (lane < 4) {
            atomicAdd(&g_sum1[c], s0);
            atomicAdd(&g_sum1[c + 1], s1);
            atomicAdd(&g_sq1[c], q0);
            atomicAdd(&g_sq1[c + 1], q1);
        }
    }
}

__global__ void k_fin1(const float* __restrict__ gamma, const float* __restrict__ beta,
                       float invN) {
    int c = threadIdx.x;
    float mean = g_sum1[c] * invN;
    float var = g_sq1[c] * invN - mean * mean;
    float sc = gamma[c] * rsqrtf(var + 1e-5f);
    g_scale1[c] = sc;
    g_shift1[c] = beta[c] - mean * sc;
}

// y2 = relu(h1*scale1+shift1) @ W2 ; also init agg2 = y2.
__global__ void __launch_bounds__(128) k_gemm2(const float* __restrict__ W2, int M) {
    __shared__ float As[64][33];
    __shared__ float Bs[32][DOUT];
    int tid = threadIdx.x;
    int cx = tid & 7, ry = tid >> 3;
    int row0 = blockIdx.x * 64;

    float acc[4][5];
#pragma unroll
    for (int i = 0; i < 4; i++)
#pragma unroll
        for (int j = 0; j < 5; j++) acc[i][j] = 0.f;

    for (int kt = 0; kt < 8; kt++) {
        int k0 = kt * 32;
#pragma unroll
        for (int j = 0; j < 16; j++) {           // A tile 64x32, normalized + relu
            int idx = tid + 128 * j;
            int m = idx >> 5, k = idx & 31;
            int r = row0 + m;
            float v = 0.f;
            if (r < M) {
                v = g_h1[(size_t)r * DHID + k0 + k];
                v = fmaxf(fmaf(v, g_scale1[k0 + k], g_shift1[k0 + k]), 0.f);
            }
            As[m][k] = v;
        }
#pragma unroll
        for (int j = 0; j < 10; j++) {           // B tile 32x40
            int idx = tid + 128 * j;
            int k = idx / 40, n = idx - k * 40;
            Bs[k][n] = W2[(k0 + k) * DOUT + n];
        }
        __syncthreads();
#pragma unroll
        for (int k = 0; k < 32; k++) {
            float a[4], b[5];
#pragma unroll
            for (int i = 0; i < 4; i++) a[i] = As[ry * 4 + i][k];
#pragma unroll
            for (int j = 0; j < 5; j++) b[j] = Bs[k][cx * 5 + j];
#pragma unroll
            for (int i = 0; i < 4; i++)
#pragma unroll
                for (int j = 0; j < 5; j++) acc[i][j] = fmaf(a[i], b[j], acc[i][j]);
        }
        __syncthreads();
    }
#pragma unroll
    for (int i = 0; i < 4; i++) {
        int r = row0 + ry * 4 + i;
        if (r < M) {
#pragma unroll
            for (int j = 0; j < 5; j++) {
                int o = r * DOUT + cx * 5 + j;
                float v = acc[i][j];
                g_y2[o] = v;
                g_agg2[o] = v;
            }
        }
    }
}

// agg2[dst] += y2[src], 10 float4 per edge
__global__ void k_scatter2(const void* __restrict__ ei, int E, int items) {
    int idx = blockIdx.x * blockDim.x + threadIdx.x;
    if (idx >= items) return;
    int e = idx / 10, c = idx - e * 10;
    int s, d;
    load_edge(ei, E, e, s, d);
    float4 v = ((const float4*)g_y2)[s * 10 + c];
    red_add_v4(&g_agg2[d * DOUT + c * 4], v);
}

// column sums / sumsq of agg2 (40 cols)
__global__ void k_stats2(int M) {
    __shared__ float ssum[160], ssq[160];
    int t = threadIdx.x;
    int c = t % 40, rr = t / 40;
    int rpb = (M + gridDim.x - 1) / gridDim.x;
    int r0 = blockIdx.x * rpb;
    int r1 = min(r0 + rpb, M);
    float s = 0.f, q = 0.f;
    for (int r = r0 + rr; r < r1; r += 4) {
        float v = g_agg2[r * DOUT + c];
        s += v; q = fmaf(v, v, q);
    }
    ssum[t] = s; ssq[t] = q;
    __syncthreads();
    if (t < 40) {
        float S = ssum[t] + ssum[t + 40] + ssum[t + 80] + ssum[t + 120];
        float Q = ssq[t] + ssq[t + 40] + ssq[t + 80] + ssq[t + 120];
        atomicAdd(&g_sum2[t], S);
        atomicAdd(&g_sq2[t], Q);
    }
}

__global__ void k_fin2(const float* __restrict__ gamma, const float* __restrict__ beta,
                       float invN) {
    int c = threadIdx.x;
    if (c >= DOUT) return;
    float mean = g_sum2[c] * invN;
    float var = g_sq2[c] * invN - mean * mean;
    float sc = gamma[c] * rsqrtf(var + 1e-5f);
    g_sc2[c] = sc;
    g_sh2[c] = beta[c] - mean * sc;
}

// per-row normalize + log_softmax; one warp per row
__global__ void k_logsoftmax(float* __restrict__ out, int M) {
    int w = (blockIdx.x * blockDim.x + threadIdx.x) >> 5;
    int l = threadIdx.x & 31;
    if (w >= M) return;
    const float* a = &g_agg2[w * DOUT];
    float v0 = fmaf(a[l], g_sc2[l], g_sh2[l]);
    float v1 = (l < 8) ? fmaf(a[32 + l], g_sc2[32 + l], g_sh2[32 + l]) : -1e30f;
    float m = fmaxf(v0, v1);
#pragma unroll
    for (int o = 16; o > 0; o >>= 1) m = fmaxf(m, __shfl_xor_sync(0xffffffffu, m, o));
    float e = expf(v0 - m) + ((l < 8) ? expf(v1 - m) : 0.f);
#pragma unroll
    for (int o = 16; o > 0; o >>= 1) e += __shfl_xor_sync(0xffffffffu, e, o);
    float ls = m + logf(e);
    out[w * DOUT + l] = v0 - ls;
    if (l < 8) out[w * DOUT + 32 + l] = v1 - ls;
}

// ---------------- launch ----------------
extern "C" void kernel_launch(void* const* d_in, const int* in_sizes, int n_in,
                              void* d_out, int out_size) {
    const float* x      = (const float*)d_in[0];
    const void*  ei     = d_in[1];
    const float* W1     = (const float*)d_in[2];
    const float* W2     = (const float*)d_in[4];
    const float* gamma1 = (const float*)d_in[6];
    const float* beta1  = (const float*)d_in[7];
    const float* gamma2 = (const float*)d_in[8];
    const float* beta2  = (const float*)d_in[9];
    float* out = (float*)d_out;

    int N = in_sizes[0] / DIN;     // 50000
    int E = in_sizes[1] / 2;       // 800000
    float invN = 1.0f / (float)N;

    static int smem_set = 0;
    size_t smem_bytes = (size_t)(128 * AS_STRIDE + KPAD * BS_STRIDE) * sizeof(float);
    if (!smem_set) {
        cudaFuncSetAttribute(k_gemm1_tf32, cudaFuncAttributeMaxDynamicSharedMemorySize,
                             (int)smem_bytes);
        smem_set = 1;
    }

    k_detect<<<1, 32>>>((const int*)ei);
    k_zero_stats<<<1, 256>>>();

    int n4 = N * DIN / 4;
    k_copy_x<<<(n4 + 255) / 256, 256>>>((const float4*)x, n4);

    int it1 = E * 25;
    k_scatter1<<<(it1 + 255) / 256, 256>>>(x, ei, E, it1);

    dim3 g1((N + 127) / 128, 2);
    k_gemm1_tf32<<<g1, 256, smem_bytes>>>(W1, N);

    k_fin1<<<1, DHID>>>(gamma1, beta1, invN);

    k_gemm2<<<(N + 63) / 64, 128>>>(W2, N);

    int it2 = E * 10;
    k_scatter2<<<(it2 + 255) / 256, 256>>>(ei, E, it2);

    k_stats2<<<128, 160>>>(N);
    k_fin2<<<1, 64>>>(gamma2, beta2, invN);

    k_logsoftmax<<<(N + 7) / 8, 256>>>(out, N);
}

// round 3
// speedup vs baseline: 1.3923x; 1.1841x over previous
#include <cuda_runtime.h>
#include <math.h>

#define NN   50000
#define DIN  100
#define DHID 256
#define DOUT 40

// ---------------- scratch ----------------
__device__ float g_agg1[(size_t)NN * DIN];
__device__ float g_h1  [(size_t)NN * DHID];
__device__ float g_y2  [(size_t)NN * DOUT];
__device__ float g_agg2[(size_t)NN * DOUT];
__device__ float g_sum1[DHID], g_sq1[DHID], g_scale1[DHID], g_shift1[DHID];
__device__ float g_sum2[DOUT], g_sq2[DOUT], g_sc2[DOUT], g_sh2[DOUT];
__device__ int   g_ei64;

// ---------------- helpers ----------------
__device__ __forceinline__ void red_add_v4(float* p, float4 v) {
    asm volatile("red.global.add.v4.f32 [%0], {%1,%2,%3,%4};"
                 :: "l"(p), "f"(v.x), "f"(v.y), "f"(v.z), "f"(v.w) : "memory");
}

__device__ __forceinline__ void load_edge(const void* ei, int E, int e, int& s, int& d) {
    if (g_ei64) {
        const long long* p = (const long long*)ei;
        s = (int)p[e]; d = (int)p[E + e];
    } else {
        const int* p = (const int*)ei;
        s = p[e]; d = p[E + e];
    }
}

__device__ __forceinline__ unsigned f2tf(float f) {
    unsigned r;
    asm("cvt.rna.tf32.f32 %0, %1;" : "=r"(r) : "f"(f));
    return r;
}

// ---------------- init: detect dtype + zero stats ----------------
__global__ void k_init(const int* ei) {
    int t = threadIdx.x;
    if (t < 32) {
        int v = ei[2 * t + 1];
        unsigned b = __ballot_sync(0xffffffffu, v == 0);
        if (t == 0) g_ei64 = (b == 0xffffffffu) ? 1 : 0;
    }
    if (t < DHID) { g_sum1[t] = 0.f; g_sq1[t] = 0.f; }
    if (t < DOUT) { g_sum2[t] = 0.f; g_sq2[t] = 0.f; }
}

// agg1 = x
__global__ void k_copy_x(const float4* __restrict__ x, int n4) {
    int i = blockIdx.x * blockDim.x + threadIdx.x;
    if (i < n4) ((float4*)g_agg1)[i] = x[i];
}

// ---- scatter1: warp handles 32 edges; lanes 0-24 move one float4 each ----
__global__ void k_scatter1(const float* __restrict__ x, const void* __restrict__ ei, int E) {
    int w = (blockIdx.x * blockDim.x + threadIdx.x) >> 5;
    int lane = threadIdx.x & 31;
    int e0 = w << 5;
    if (e0 >= E) return;
    int s = 0, d = 0;
    int e = e0 + lane;
    if (e < E) load_edge(ei, E, e, s, d);
    int n = min(32, E - e0);
    if (n == 32) {
#pragma unroll 4
        for (int j = 0; j < 32; j++) {
            int sj = __shfl_sync(0xffffffffu, s, j);
            int dj = __shfl_sync(0xffffffffu, d, j);
            if (lane < 25) {
                float4 v = ((const float4*)x)[sj * 25 + lane];
                red_add_v4(&g_agg1[dj * DIN + lane * 4], v);
            }
        }
    } else {
        for (int j = 0; j < n; j++) {
            int sj = __shfl_sync(0xffffffffu, s, j);
            int dj = __shfl_sync(0xffffffffu, d, j);
            if (lane < 25) {
                float4 v = ((const float4*)x)[sj * 25 + lane];
                red_add_v4(&g_agg1[dj * DIN + lane * 4], v);
            }
        }
    }
}

// ---- gemm1: h1 = agg1 @ W1 via tf32 mma, fused BN stats ----
#define AS_STRIDE 108
#define BS_STRIDE 136
#define KPAD 104

__global__ void __launch_bounds__(256) k_gemm1_tf32(const float* __restrict__ W1, int M) {
    extern __shared__ unsigned sm[];
    unsigned* As = sm;                      // 128*108
    unsigned* Bs = sm + 128 * AS_STRIDE;    // 104*136

    int tid = threadIdx.x;
    int lane = tid & 31, warp = tid >> 5;
    int warp_m = warp >> 1;
    int warp_n = warp & 1;
    int grp = lane >> 2, qd = lane & 3;
    int row0 = blockIdx.x * 128, col0 = blockIdx.y * 128;

    {
        int m = tid >> 1, h = tid & 1;
        int r = row0 + m;
        unsigned* dst = &As[m * AS_STRIDE + h * 52];
        if (r < M) {
            const float4* src = (const float4*)&g_agg1[r * DIN + h * 52];
            int nv4 = h ? 12 : 13;
#pragma unroll
            for (int i = 0; i < 13; i++) {
                if (i < nv4) {
                    float4 v = src[i];
                    dst[i * 4 + 0] = f2tf(v.x);
                    dst[i * 4 + 1] = f2tf(v.y);
                    dst[i * 4 + 2] = f2tf(v.z);
                    dst[i * 4 + 3] = f2tf(v.w);
                }
            }
            if (h) { dst[48] = 0; dst[49] = 0; dst[50] = 0; dst[51] = 0; }
        } else {
#pragma unroll
            for (int i = 0; i < 52; i++) dst[i] = 0;
        }
    }
    if (tid < 208) {
        int k = tid >> 1, h = tid & 1;
        unsigned* dst = &Bs[k * BS_STRIDE + h * 64];
        if (k < DIN) {
            const float4* src = (const float4*)&W1[k * DHID + col0 + h * 64];
#pragma unroll
            for (int i = 0; i < 16; i++) {
                float4 v = src[i];
                dst[i * 4 + 0] = f2tf(v.x);
                dst[i * 4 + 1] = f2tf(v.y);
                dst[i * 4 + 2] = f2tf(v.z);
                dst[i * 4 + 3] = f2tf(v.w);
            }
        } else {
#pragma unroll
            for (int i = 0; i < 64; i++) dst[i] = 0;
        }
    }
    __syncthreads();

    float acc[2][8][4];
#pragma unroll
    for (int mt = 0; mt < 2; mt++)
#pragma unroll
        for (int nt = 0; nt < 8; nt++)
#pragma unroll
            for (int j = 0; j < 4; j++) acc[mt][nt][j] = 0.f;

    for (int ks = 0; ks < KPAD / 8; ks++) {
        int k0 = ks * 8;
        unsigned a[2][4];
#pragma unroll
        for (int mt = 0; mt < 2; mt++) {
            const unsigned* Ar  = &As[(warp_m * 32 + mt * 16 + grp) * AS_STRIDE + k0 + qd];
            const unsigned* Ar8 = Ar + 8 * AS_STRIDE;
            a[mt][0] = Ar[0];  a[mt][1] = Ar8[0];
            a[mt][2] = Ar[4];  a[mt][3] = Ar8[4];
        }
#pragma unroll
        for (int nt = 0; nt < 8; nt++) {
            const unsigned* Bp = &Bs[(k0 + qd) * BS_STRIDE + warp_n * 64 + nt * 8 + grp];
            unsigned b0 = Bp[0];
            unsigned b1 = Bp[4 * BS_STRIDE];
#pragma unroll
            for (int mt = 0; mt < 2; mt++) {
                asm volatile(
                    "mma.sync.aligned.m16n8k8.row.col.f32.tf32.tf32.f32 "
                    "{%0,%1,%2,%3},{%4,%5,%6,%7},{%8,%9},{%0,%1,%2,%3};"
                    : "+f"(acc[mt][nt][0]), "+f"(acc[mt][nt][1]),
                      "+f"(acc[mt][nt][2]), "+f"(acc[mt][nt][3])
                    : "r"(a[mt][0]), "r"(a[mt][1]), "r"(a[mt][2]), "r"(a[mt][3]),
                      "r"(b0), "r"(b1));
            }
        }
    }

#pragma unroll
    for (int nt = 0; nt < 8; nt++) {
        int c = col0 + warp_n * 64 + nt * 8 + 2 * qd;
        float s0 = 0.f, s1 = 0.f, q0 = 0.f, q1 = 0.f;
#pragma unroll
        for (int mt = 0; mt < 2; mt++) {
            int r = row0 + warp_m * 32 + mt * 16 + grp;
            float d0 = acc[mt][nt][0], d1 = acc[mt][nt][1];
            float d2 = acc[mt][nt][2], d3 = acc[mt][nt][3];
            if (r < M)     *(float2*)&g_h1[(size_t)r * DHID + c] = make_float2(d0, d1);
            if (r + 8 < M) *(float2*)&g_h1[(size_t)(r + 8) * DHID + c] = make_float2(d2, d3);
            s0 += d0 + d2;  s1 += d1 + d3;
            q0 = fmaf(d0, d0, fmaf(d2, d2, q0));
            q1 = fmaf(d1, d1, fmaf(d3, d3, q1));
        }
#pragma unroll
        for (int o = 4; o < 32; o <<= 1) {
            s0 += __shfl_xor_sync(0xffffffffu, s0, o);
            s1 += __shfl_xor_sync(0xffffffffu, s1, o);
            q0 += __shfl_xor_sync(0xffffffffu, q0, o);
            q1 += __shfl_xor_sync(0xffffffffu, q1, o);
        }
        if (lane < 4) {
            atomicAdd(&g_sum1[c], s0);
            atomicAdd(&g_sum1[c + 1], s1);
            atomicAdd(&g_sq1[c], q0);
            atomicAdd(&g_sq1[c + 1], q1);
        }
    }
}

__global__ void k_fin1(const float* __restrict__ gamma, const float* __restrict__ beta,
                       float invN) {
    int c = threadIdx.x;
    float mean = g_sum1[c] * invN;
    float var = g_sq1[c] * invN - mean * mean;
    float sc = gamma[c] * rsqrtf(var + 1e-5f);
    g_scale1[c] = sc;
    g_shift1[c] = beta[c] - mean * sc;
}

// ---- gemm2: y2 = relu(BN(h1)) @ W2 via tf32 mma; full B resident ----
#define G2_AST 68
__global__ void __launch_bounds__(256) k_gemm2_tf32(const float* __restrict__ W2, int M) {
    extern __shared__ unsigned sm2[];
    unsigned* As = sm2;                        // 128*68
    unsigned* Bs = sm2 + 128 * G2_AST;         // 256*40
    float* ssc = (float*)(Bs + 256 * DOUT);    // 256
    float* ssh = ssc + 256;                    // 256

    int tid = threadIdx.x;
    int lane = tid & 31, warp = tid >> 5;
    int grp = lane >> 2, qd = lane & 3;
    int row0 = blockIdx.x * 128;

    ssc[tid] = g_scale1[tid];
    ssh[tid] = g_shift1[tid];
#pragma unroll
    for (int i = 0; i < 40; i++) {
        int idx = tid + 256 * i;               // 256*40 = 10240 exact
        Bs[idx] = f2tf(W2[idx]);
    }
    __syncthreads();

    float acc[5][4];
#pragma unroll
    for (int nt = 0; nt < 5; nt++)
#pragma unroll
        for (int j = 0; j < 4; j++) acc[nt][j] = 0.f;

    for (int st = 0; st < 4; st++) {
        int k0 = st * 64;
        if (st) __syncthreads();
        {
            int m = tid >> 1, h = (tid & 1) * 32;
            int r = row0 + m;
            unsigned* dst = &As[m * G2_AST + h];
            if (r < M) {
                const float4* src = (const float4*)&g_h1[(size_t)r * DHID + k0 + h];
#pragma unroll
                for (int i = 0; i < 8; i++) {
                    float4 v = src[i];
                    int c = k0 + h + i * 4;
                    dst[i * 4 + 0] = f2tf(fmaxf(fmaf(v.x, ssc[c + 0], ssh[c + 0]), 0.f));
                    dst[i * 4 + 1] = f2tf(fmaxf(fmaf(v.y, ssc[c + 1], ssh[c + 1]), 0.f));
                    dst[i * 4 + 2] = f2tf(fmaxf(fmaf(v.z, ssc[c + 2], ssh[c + 2]), 0.f));
                    dst[i * 4 + 3] = f2tf(fmaxf(fmaf(v.w, ssc[c + 3], ssh[c + 3]), 0.f));
                }
            } else {
#pragma unroll
                for (int i = 0; i < 32; i++) dst[i] = 0;
            }
        }
        __syncthreads();
#pragma unroll
        for (int ks = 0; ks < 8; ks++) {
            int kk = ks * 8;
            const unsigned* Ar = &As[(warp * 16 + grp) * G2_AST + kk + qd];
            unsigned a0 = Ar[0], a1 = Ar[8 * G2_AST], a2 = Ar[4], a3 = Ar[8 * G2_AST + 4];
#pragma unroll
            for (int nt = 0; nt < 5; nt++) {
                const unsigned* Bp = &Bs[(k0 + kk + qd) * DOUT + nt * 8 + grp];
                unsigned b0 = Bp[0];
                unsigned b1 = Bp[4 * DOUT];
                asm volatile(
                    "mma.sync.aligned.m16n8k8.row.col.f32.tf32.tf32.f32 "
                    "{%0,%1,%2,%3},{%4,%5,%6,%7},{%8,%9},{%0,%1,%2,%3};"
                    : "+f"(acc[nt][0]), "+f"(acc[nt][1]),
                      "+f"(acc[nt][2]), "+f"(acc[nt][3])
                    : "r"(a0), "r"(a1), "r"(a2), "r"(a3), "r"(b0), "r"(b1));
            }
        }
    }

    int r = row0 + warp * 16 + grp;
#pragma unroll
    for (int nt = 0; nt < 5; nt++) {
        int c = nt * 8 + 2 * qd;
        if (r < M) {
            float2 v = make_float2(acc[nt][0], acc[nt][1]);
            *(float2*)&g_y2[r * DOUT + c] = v;
            *(float2*)&g_agg2[r * DOUT + c] = v;
        }
        if (r + 8 < M) {
            float2 v = make_float2(acc[nt][2], acc[nt][3]);
            *(float2*)&g_y2[(r + 8) * DOUT + c] = v;
            *(float2*)&g_agg2[(r + 8) * DOUT + c] = v;
        }
    }
}

// ---- scatter2: warp handles 32 edges; 3 edges x 10 chunks per iter ----
__global__ void k_scatter2(const void* __restrict__ ei, int E) {
    int w = (blockIdx.x * blockDim.x + threadIdx.x) >> 5;
    int lane = threadIdx.x & 31;
    int e0 = w << 5;
    if (e0 >= E) return;
    int s = 0, d = 0;
    int e = e0 + lane;
    if (e < E) load_edge(ei, E, e, s, d);
    int n = min(32, E - e0);
    int sub = lane / 10;
    int ch = lane - sub * 10;
#pragma unroll
    for (int j = 0; j < 32; j += 3) {
        int ee = j + sub;
        int eec = min(ee, 31);
        int sj = __shfl_sync(0xffffffffu, s, eec);
        int dj = __shfl_sync(0xffffffffu, d, eec);
        if (sub < 3 && ee < n) {
            float4 v = ((const float4*)g_y2)[sj * 10 + ch];
            red_add_v4(&g_agg2[dj * DOUT + ch * 4], v);
        }
    }
}

// column sums / sumsq of agg2
__global__ void k_stats2(int M) {
    __shared__ float ssum[160], ssq[160];
    int t = threadIdx.x;
    int c = t % 40, rr = t / 40;
    int rpb = (M + gridDim.x - 1) / gridDim.x;
    int r0 = blockIdx.x * rpb;
    int r1 = min(r0 + rpb, M);
    float s = 0.f, q = 0.f;
    for (int r = r0 + rr; r < r1; r += 4) {
        float v = g_agg2[r * DOUT + c];
        s += v; q = fmaf(v, v, q);
    }
    ssum[t] = s; ssq[t] = q;
    __syncthreads();
    if (t < 40) {
        float S = ssum[t] + ssum[t + 40] + ssum[t + 80] + ssum[t + 120];
        float Q = ssq[t] + ssq[t + 40] + ssq[t + 80] + ssq[t + 120];
        atomicAdd(&g_sum2[t], S);
        atomicAdd(&g_sq2[t], Q);
    }
}

__global__ void k_fin2(const float* __restrict__ gamma, const float* __restrict__ beta,
                       float invN) {
    int c = threadIdx.x;
    if (c >= DOUT) return;
    float mean = g_sum2[c] * invN;
    float var = g_sq2[c] * invN - mean * mean;
    float sc = gamma[c] * rsqrtf(var + 1e-5f);
    g_sc2[c] = sc;
    g_sh2[c] = beta[c] - mean * sc;
}

__global__ void k_logsoftmax(float* __restrict__ out, int M) {
    int w = (blockIdx.x * blockDim.x + threadIdx.x) >> 5;
    int l = threadIdx.x & 31;
    if (w >= M) return;
    const float* a = &g_agg2[w * DOUT];
    float v0 = fmaf(a[l], g_sc2[l], g_sh2[l]);
    float v1 = (l < 8) ? fmaf(a[32 + l], g_sc2[32 + l], g_sh2[32 + l]) : -1e30f;
    float m = fmaxf(v0, v1);
#pragma unroll
    for (int o = 16; o > 0; o >>= 1) m = fmaxf(m, __shfl_xor_sync(0xffffffffu, m, o));
    float e = expf(v0 - m) + ((l < 8) ? expf(v1 - m) : 0.f);
#pragma unroll
    for (int o = 16; o > 0; o >>= 1) e += __shfl_xor_sync(0xffffffffu, e, o);
    float ls = m + logf(e);
    out[w * DOUT + l] = v0 - ls;
    if (l < 8) out[w * DOUT + 32 + l] = v1 - ls;
}

// ---------------- launch ----------------
extern "C" void kernel_launch(void* const* d_in, const int* in_sizes, int n_in,
                              void* d_out, int out_size) {
    const float* x      = (const float*)d_in[0];
    const void*  ei     = d_in[1];
    const float* W1     = (const float*)d_in[2];
    const float* W2     = (const float*)d_in[4];
    const float* gamma1 = (const float*)d_in[6];
    const float* beta1  = (const float*)d_in[7];
    const float* gamma2 = (const float*)d_in[8];
    const float* beta2  = (const float*)d_in[9];
    float* out = (float*)d_out;

    int N = in_sizes[0] / DIN;     // 50000
    int E = in_sizes[1] / 2;       // 800000
    float invN = 1.0f / (float)N;

    size_t smem1 = (size_t)(128 * AS_STRIDE + KPAD * BS_STRIDE) * sizeof(float);
    size_t smem2 = (size_t)(128 * G2_AST + 256 * DOUT + 512) * sizeof(float);
    static int smem_set = 0;
    if (!smem_set) {
        cudaFuncSetAttribute(k_gemm1_tf32, cudaFuncAttributeMaxDynamicSharedMemorySize,
                             (int)smem1);
        cudaFuncSetAttribute(k_gemm2_tf32, cudaFuncAttributeMaxDynamicSharedMemorySize,
                             (int)smem2);
        smem_set = 1;
    }

    k_init<<<1, 256>>>((const int*)ei);

    int n4 = N * DIN / 4;
    k_copy_x<<<(n4 + 255) / 256, 256>>>((const float4*)x, n4);

    int nwarps = (E + 31) / 32;
    int nthreads = nwarps * 32;
    k_scatter1<<<(nthreads + 255) / 256, 256>>>(x, ei, E);

    dim3 g1((N + 127) / 128, 2);
    k_gemm1_tf32<<<g1, 256, smem1>>>(W1, N);

    k_fin1<<<1, DHID>>>(gamma1, beta1, invN);

    k_gemm2_tf32<<<(N + 127) / 128, 256, smem2>>>(W2, N);

    k_scatter2<<<(nthreads + 255) / 256, 256>>>(ei, E);

    k_stats2<<<128, 160>>>(N);
    k_fin2<<<1, 64>>>(gamma2, beta2, invN);

    k_logsoftmax<<<(N + 7) / 8, 256>>>(out, N);
}

// round 5
// speedup vs baseline: 1.4861x; 1.0674x over previous
#include <cuda_runtime.h>
#include <cstdint>
#include <math.h>

#define NN   50000
#define DIN  100
#define DHID 256
#define DOUT 40

// ---------------- scratch ----------------
__device__ float g_agg1[(size_t)NN * DIN];
__device__ float g_h1  [(size_t)NN * DHID];
__device__ float g_y2  [(size_t)NN * DOUT];
__device__ float g_agg2[(size_t)NN * DOUT];
__device__ float g_sum1[DHID], g_sq1[DHID];
__device__ float g_sum2[DOUT], g_sq2[DOUT];
__device__ int   g_ei64;

// ---------------- helpers ----------------
__device__ __forceinline__ void red_add_v4(float* p, float4 v) {
    asm volatile("red.global.add.v4.f32 [%0], {%1,%2,%3,%4};"
                 :: "l"(p), "f"(v.x), "f"(v.y), "f"(v.z), "f"(v.w) : "memory");
}

__device__ __forceinline__ void load_edge(const void* ei, int E, int e, int& s, int& d) {
    if (g_ei64) {
        const long long* p = (const long long*)ei;
        s = (int)p[e]; d = (int)p[E + e];
    } else {
        const int* p = (const int*)ei;
        s = p[e]; d = p[E + e];
    }
}

__device__ __forceinline__ void cp_async16(unsigned dst, const void* src, int src_bytes) {
    asm volatile("cp.async.cg.shared.global [%0], [%1], 16, %2;"
                 :: "r"(dst), "l"(src), "r"(src_bytes));
}
__device__ __forceinline__ void cp_async_commit_wait() {
    asm volatile("cp.async.commit_group;\n\tcp.async.wait_group 0;" ::: "memory");
}

// ---------------- init ----------------
__global__ void k_init(const int* ei) {
    int t = threadIdx.x;
    if (t < 32) {
        int v = ei[2 * t + 1];
        unsigned b = __ballot_sync(0xffffffffu, v == 0);
        if (t == 0) g_ei64 = (b == 0xffffffffu) ? 1 : 0;
    }
    if (t < DHID) { g_sum1[t] = 0.f; g_sq1[t] = 0.f; }
    if (t < DOUT) { g_sum2[t] = 0.f; g_sq2[t] = 0.f; }
}

// agg1 = x
__global__ void k_copy_x(const float4* __restrict__ x, int n4) {
    int i = blockIdx.x * blockDim.x + threadIdx.x;
    if (i < n4) ((float4*)g_agg1)[i] = x[i];
}

// ---- scatter1: warp handles 32 edges; lanes 0-24 move one float4 each ----
__global__ void k_scatter1(const float* __restrict__ x, const void* __restrict__ ei, int E) {
    int w = (blockIdx.x * blockDim.x + threadIdx.x) >> 5;
    int lane = threadIdx.x & 31;
    int e0 = w << 5;
    if (e0 >= E) return;
    int s = 0, d = 0;
    int e = e0 + lane;
    if (e < E) load_edge(ei, E, e, s, d);
    int n = min(32, E - e0);
    if (n == 32) {
#pragma unroll 4
        for (int j = 0; j < 32; j++) {
            int sj = __shfl_sync(0xffffffffu, s, j);
            int dj = __shfl_sync(0xffffffffu, d, j);
            if (lane < 25) {
                float4 v = ((const float4*)x)[sj * 25 + lane];
                red_add_v4(&g_agg1[dj * DIN + lane * 4], v);
            }
        }
    } else {
        for (int j = 0; j < n; j++) {
            int sj = __shfl_sync(0xffffffffu, s, j);
            int dj = __shfl_sync(0xffffffffu, d, j);
            if (lane < 25) {
                float4 v = ((const float4*)x)[sj * 25 + lane];
                red_add_v4(&g_agg1[dj * DIN + lane * 4], v);
            }
        }
    }
}

// ---- gemm1: h1 = agg1 @ W1 via tf32 mma (raw-fp32 truncation), cp.async loads,
//      fused BN stats ----
#define AS_STRIDE 108
#define BS_STRIDE 136
#define KPAD 104

__global__ void __launch_bounds__(256) k_gemm1_tf32(const float* __restrict__ W1, int M) {
    extern __shared__ unsigned sm[];
    unsigned* As = sm;                      // 128*108
    unsigned* Bs = sm + 128 * AS_STRIDE;    // 104*136

    int tid = threadIdx.x;
    int lane = tid & 31, warp = tid >> 5;
    int warp_m = warp >> 1;
    int warp_n = warp & 1;
    int grp = lane >> 2, qd = lane & 3;
    int row0 = blockIdx.x * 128, col0 = blockIdx.y * 128;

    // ---- A tile via cp.async: thread -> row m=tid>>1, half h=tid&1 (52 words) ----
    {
        int m = tid >> 1, h = tid & 1;
        int r = row0 + m;
        bool rv = (r < M);
        unsigned dst = (unsigned)__cvta_generic_to_shared(&As[m * AS_STRIDE + h * 52]);
        const float* src = &g_agg1[(size_t)(rv ? r : 0) * DIN + h * 52];
#pragma unroll
        for (int i = 0; i < 13; i++) {
            int sz = (rv && (h == 0 || i < 12)) ? 16 : 0;  // cols 100..103 -> zero
            cp_async16(dst + i * 16, src + i * 4, sz);
        }
    }
    // ---- B tile via cp.async: 3328 chunks of 16B over 256 threads x 13 ----
    {
#pragma unroll
        for (int i = 0; i < 13; i++) {
            int cid = tid + 256 * i;
            int k = cid >> 5, c4 = (cid & 31) * 4;
            unsigned dst = (unsigned)__cvta_generic_to_shared(&Bs[k * BS_STRIDE + c4]);
            const float* src = &W1[(k < DIN ? k : 0) * DHID + col0 + c4];
            cp_async16(dst, src, (k < DIN) ? 16 : 0);
        }
    }
    cp_async_commit_wait();
    __syncthreads();

    float acc[2][8][4];
#pragma unroll
    for (int mt = 0; mt < 2; mt++)
#pragma unroll
        for (int nt = 0; nt < 8; nt++)
#pragma unroll
            for (int j = 0; j < 4; j++) acc[mt][nt][j] = 0.f;

    for (int ks = 0; ks < KPAD / 8; ks++) {
        int k0 = ks * 8;
        unsigned a[2][4];
#pragma unroll
        for (int mt = 0; mt < 2; mt++) {
            const unsigned* Ar  = &As[(warp_m * 32 + mt * 16 + grp) * AS_STRIDE + k0 + qd];
            const unsigned* Ar8 = Ar + 8 * AS_STRIDE;
            a[mt][0] = Ar[0];  a[mt][1] = Ar8[0];
            a[mt][2] = Ar[4];  a[mt][3] = Ar8[4];
        }
#pragma unroll
        for (int nt = 0; nt < 8; nt++) {
            const unsigned* Bp = &Bs[(k0 + qd) * BS_STRIDE + warp_n * 64 + nt * 8 + grp];
            unsigned b0 = Bp[0];
            unsigned b1 = Bp[4 * BS_STRIDE];
#pragma unroll
            for (int mt = 0; mt < 2; mt++) {
                asm volatile(
                    "mma.sync.aligned.m16n8k8.row.col.f32.tf32.tf32.f32 "
                    "{%0,%1,%2,%3},{%4,%5,%6,%7},{%8,%9},{%0,%1,%2,%3};"
                    : "+f"(acc[mt][nt][0]), "+f"(acc[mt][nt][1]),
                      "+f"(acc[mt][nt][2]), "+f"(acc[mt][nt][3])
                    : "r"(a[mt][0]), "r"(a[mt][1]), "r"(a[mt][2]), "r"(a[mt][3]),
                      "r"(b0), "r"(b1));
            }
        }
    }

#pragma unroll
    for (int nt = 0; nt < 8; nt++) {
        int c = col0 + warp_n * 64 + nt * 8 + 2 * qd;
        float s0 = 0.f, s1 = 0.f, q0 = 0.f, q1 = 0.f;
#pragma unroll
        for (int mt = 0; mt < 2; mt++) {
            int r = row0 + warp_m * 32 + mt * 16 + grp;
            float d0 = acc[mt][nt][0], d1 = acc[mt][nt][1];
            float d2 = acc[mt][nt][2], d3 = acc[mt][nt][3];
            if (r < M)     *(float2*)&g_h1[(size_t)r * DHID + c] = make_float2(d0, d1);
            if (r + 8 < M) *(float2*)&g_h1[(size_t)(r + 8) * DHID + c] = make_float2(d2, d3);
            s0 += d0 + d2;  s1 += d1 + d3;
            q0 = fmaf(d0, d0, fmaf(d2, d2, q0));
            q1 = fmaf(d1, d1, fmaf(d3, d3, q1));
        }
#pragma unroll
        for (int o = 4; o < 32; o <<= 1) {
            s0 += __shfl_xor_sync(0xffffffffu, s0, o);
            s1 += __shfl_xor_sync(0xffffffffu, s1, o);
            q0 += __shfl_xor_sync(0xffffffffu, q0, o);
            q1 += __shfl_xor_sync(0xffffffffu, q1, o);
        }
        if (lane < 4) {
            atomicAdd(&g_sum1[c], s0);
            atomicAdd(&g_sum1[c + 1], s1);
            atomicAdd(&g_sq1[c], q0);
            atomicAdd(&g_sq1[c + 1], q1);
        }
    }
}

// ---- gemm2: y2 = relu(BN(h1)) @ W2 via tf32 mma; fin1 fused in prologue ----
#define G2_AST 68
__global__ void __launch_bounds__(256) k_gemm2_tf32(const float* __restrict__ W2,
                                                    const float* __restrict__ gamma1,
                                                    const float* __restrict__ beta1,
                                                    float invN, int M) {
    extern __shared__ unsigned sm2[];
    unsigned* As = sm2;                        // 128*68
    unsigned* Bs = sm2 + 128 * G2_AST;         // 256*40
    float* ssc = (float*)(Bs + 256 * DOUT);    // 256
    float* ssh = ssc + 256;                    // 256

    int tid = threadIdx.x;
    int lane = tid & 31, warp = tid >> 5;
    int grp = lane >> 2, qd = lane & 3;
    int row0 = blockIdx.x * 128;

    {   // fused fin1
        float mean = g_sum1[tid] * invN;
        float var = g_sq1[tid] * invN - mean * mean;
        float sc = gamma1[tid] * rsqrtf(var + 1e-5f);
        ssc[tid] = sc;
        ssh[tid] = beta1[tid] - mean * sc;
    }
#pragma unroll
    for (int i = 0; i < 40; i++) {
        int idx = tid + 256 * i;               // 256*40 exact
        Bs[idx] = __float_as_uint(W2[idx]);
    }
    __syncthreads();

    float acc[5][4];
#pragma unroll
    for (int nt = 0; nt < 5; nt++)
#pragma unroll
        for (int j = 0; j < 4; j++) acc[nt][j] = 0.f;

    for (int st = 0; st < 4; st++) {
        int k0 = st * 64;
        if (st) __syncthreads();
        {
            int m = tid >> 1, h = (tid & 1) * 32;
            int r = row0 + m;
            unsigned* dst = &As[m * G2_AST + h];
            if (r < M) {
                const float4* src = (const float4*)&g_h1[(size_t)r * DHID + k0 + h];
#pragma unroll
                for (int i = 0; i < 8; i++) {
                    float4 v = src[i];
                    int c = k0 + h + i * 4;
                    dst[i * 4 + 0] = __float_as_uint(fmaxf(fmaf(v.x, ssc[c + 0], ssh[c + 0]), 0.f));
                    dst[i * 4 + 1] = __float_as_uint(fmaxf(fmaf(v.y, ssc[c + 1], ssh[c + 1]), 0.f));
                    dst[i * 4 + 2] = __float_as_uint(fmaxf(fmaf(v.z, ssc[c + 2], ssh[c + 2]), 0.f));
                    dst[i * 4 + 3] = __float_as_uint(fmaxf(fmaf(v.w, ssc[c + 3], ssh[c + 3]), 0.f));
                }
            } else {
#pragma unroll
                for (int i = 0; i < 32; i++) dst[i] = 0;
            }
        }
        __syncthreads();
#pragma unroll
        for (int ks = 0; ks < 8; ks++) {
            int kk = ks * 8;
            const unsigned* Ar = &As[(warp * 16 + grp) * G2_AST + kk + qd];
            unsigned a0 = Ar[0], a1 = Ar[8 * G2_AST], a2 = Ar[4], a3 = Ar[8 * G2_AST + 4];
#pragma unroll
            for (int nt = 0; nt < 5; nt++) {
                const unsigned* Bp = &Bs[(k0 + kk + qd) * DOUT + nt * 8 + grp];
                unsigned b0 = Bp[0];
                unsigned b1 = Bp[4 * DOUT];
                asm volatile(
                    "mma.sync.aligned.m16n8k8.row.col.f32.tf32.tf32.f32 "
                    "{%0,%1,%2,%3},{%4,%5,%6,%7},{%8,%9},{%0,%1,%2,%3};"
                    : "+f"(acc[nt][0]), "+f"(acc[nt][1]),
                      "+f"(acc[nt][2]), "+f"(acc[nt][3])
                    : "r"(a0), "r"(a1), "r"(a2), "r"(a3), "r"(b0), "r"(b1));
            }
        }
    }

    int r = row0 + warp * 16 + grp;
#pragma unroll
    for (int nt = 0; nt < 5; nt++) {
        int c = nt * 8 + 2 * qd;
        if (r < M) {
            float2 v = make_float2(acc[nt][0], acc[nt][1]);
            *(float2*)&g_y2[r * DOUT + c] = v;
            *(float2*)&g_agg2[r * DOUT + c] = v;
        }
        if (r + 8 < M) {
            float2 v = make_float2(acc[nt][2], acc[nt][3]);
            *(float2*)&g_y2[(r + 8) * DOUT + c] = v;
            *(float2*)&g_agg2[(r + 8) * DOUT + c] = v;
        }
    }
}

// ---- scatter2 ----
__global__ void k_scatter2(const void* __restrict__ ei, int E) {
    int w = (blockIdx.x * blockDim.x + threadIdx.x) >> 5;
    int lane = threadIdx.x & 31;
    int e0 = w << 5;
    if (e0 >= E) return;
    int s = 0, d = 0;
    int e = e0 + lane;
    if (e < E) load_edge(ei, E, e, s, d);
    int n = min(32, E - e0);
    int sub = lane / 10;
    int ch = lane - sub * 10;
#pragma unroll
    for (int j = 0; j < 32; j += 3) {
        int ee = j + sub;
        int eec = min(ee, 31);
        int sj = __shfl_sync(0xffffffffu, s, eec);
        int dj = __shfl_sync(0xffffffffu, d, eec);
        if (sub < 3 && ee < n) {
            float4 v = ((const float4*)g_y2)[sj * 10 + ch];
            red_add_v4(&g_agg2[dj * DOUT + ch * 4], v);
        }
    }
}

// column sums / sumsq of agg2
__global__ void k_stats2(int M) {
    __shared__ float ssum[160], ssq[160];
    int t = threadIdx.x;
    int c = t % 40, rr = t / 40;
    int rpb = (M + gridDim.x - 1) / gridDim.x;
    int r0 = blockIdx.x * rpb;
    int r1 = min(r0 + rpb, M);
    float s = 0.f, q = 0.f;
    for (int r = r0 + rr; r < r1; r += 4) {
        float v = g_agg2[r * DOUT + c];
        s += v; q = fmaf(v, v, q);
    }
    ssum[t] = s; ssq[t] = q;
    __syncthreads();
    if (t < 40) {
        float S = ssum[t] + ssum[t + 40] + ssum[t + 80] + ssum[t + 120];
        float Q = ssq[t] + ssq[t + 40] + ssq[t + 80] + ssq[t + 120];
        atomicAdd(&g_sum2[t], S);
        atomicAdd(&g_sq2[t], Q);
    }
}

// ---- fin2 fused into log_softmax ----
__global__ void k_logsoftmax(float* __restrict__ out,
                             const float* __restrict__ gamma2,
                             const float* __restrict__ beta2,
                             float invN, int M) {
    __shared__ float sc2[DOUT], sh2[DOUT];
    int t = threadIdx.x;
    if (t < DOUT) {
        float mean = g_sum2[t] * invN;
        float var = g_sq2[t] * invN - mean * mean;
        float sc = gamma2[t] * rsqrtf(var + 1e-5f);
        sc2[t] = sc;
        sh2[t] = beta2[t] - mean * sc;
    }
    __syncthreads();
    int w = (blockIdx.x * blockDim.x + t) >> 5;
    int l = t & 31;
    if (w >= M) return;
    const float* a = &g_agg2[w * DOUT];
    float v0 = fmaf(a[l], sc2[l], sh2[l]);
    float v1 = (l < 8) ? fmaf(a[32 + l], sc2[32 + l], sh2[32 + l]) : -1e30f;
    float m = fmaxf(v0, v1);
#pragma unroll
    for (int o = 16; o > 0; o >>= 1) m = fmaxf(m, __shfl_xor_sync(0xffffffffu, m, o));
    float e = expf(v0 - m) + ((l < 8) ? expf(v1 - m) : 0.f);
#pragma unroll
    for (int o = 16; o > 0; o >>= 1) e += __shfl_xor_sync(0xffffffffu, e, o);
    float ls = m + logf(e);
    out[w * DOUT + l] = v0 - ls;
    if (l < 8) out[w * DOUT + 32 + l] = v1 - ls;
}

// ---------------- launch ----------------
extern "C" void kernel_launch(void* const* d_in, const int* in_sizes, int n_in,
                              void* d_out, int out_size) {
    const float* x      = (const float*)d_in[0];
    const void*  ei     = d_in[1];
    const float* W1     = (const float*)d_in[2];
    const float* W2     = (const float*)d_in[4];
    const float* gamma1 = (const float*)d_in[6];
    const float* beta1  = (const float*)d_in[7];
    const float* gamma2 = (const float*)d_in[8];
    const float* beta2  = (const float*)d_in[9];
    float* out = (float*)d_out;

    int N = in_sizes[0] / DIN;     // 50000
    int E = in_sizes[1] / 2;       // 800000
    float invN = 1.0f / (float)N;

    size_t smem1 = (size_t)(128 * AS_STRIDE + KPAD * BS_STRIDE) * sizeof(float);
    size_t smem2 = (size_t)(128 * G2_AST + 256 * DOUT + 512) * sizeof(float);
    static int smem_set = 0;
    if (!smem_set) {
        cudaFuncSetAttribute(k_gemm1_tf32, cudaFuncAttributeMaxDynamicSharedMemorySize,
                             (int)smem1);
        cudaFuncSetAttribute(k_gemm2_tf32, cudaFuncAttributeMaxDynamicSharedMemorySize,
                             (int)smem2);
        smem_set = 1;
    }

    k_init<<<1, 256>>>((const int*)ei);

    int n4 = N * DIN / 4;
    k_copy_x<<<(n4 + 255) / 256, 256>>>((const float4*)x, n4);

    int nwarps = (E + 31) / 32;
    int nthreads = nwarps * 32;
    k_scatter1<<<(nthreads + 255) / 256, 256>>>(x, ei, E);

    dim3 g1((N + 127) / 128, 2);
    k_gemm1_tf32<<<g1, 256, smem1>>>(W1, N);

    k_gemm2_tf32<<<(N + 127) / 128, 256, smem2>>>(W2, gamma1, beta1, invN, N);

    k_scatter2<<<(nthreads + 255) / 256, 256>>>(ei, E);

    k_stats2<<<128, 160>>>(N);

    k_logsoftmax<<<(N + 7) / 8, 256>>>(out, gamma2, beta2, invN, N);
}